// round 10
// baseline (speedup 1.0000x reference)
#include <cuda_runtime.h>
#include <cuda_bf16.h>
#include <cstdint>

#define DIN        118
#define DOUT       64
#define TILE       64
#define NPAIR      64        // padded K/2 pairs per W row
#define DATA_PAIRS 59        // DIN/2
#define THREADS    256
#define HSTRIDE    72        // floats per h row (padding vs bank conflicts)
#define XROW_BYTES 472       // 118 * 4
#define XTILE_B    (TILE * XROW_BYTES)   // 30208

// dynamic smem layout (bytes) -- tiny now: no staging
#define SM_W      0                       // bf16 [64][128] swizzled  = 16384
#define SM_H      16384                   // f32  [64][72]            = 18432
#define SM_BATCH  34816                   // int  [64] clamped        = 256
#define SMEM_TOTAL 35072

// segment-sum scratch (consumed & re-zeroed by normalize -> graph-replay safe)
#define SCRATCH_CAP (1 << 20)             // 4 MB: supports nSeg <= 16384
__device__ float g_scratch[SCRATCH_CAP];

// ---------------- helpers ----------------

__device__ __forceinline__ uint32_t smem_to_u32(const void* p) {
    uint32_t a;
    asm("{ .reg .u64 t; cvta.to.shared.u64 t, %1; cvt.u32.u64 %0, t; }"
        : "=r"(a) : "l"(p));
    return a;
}

#define CVT_BF16X2(result, lo, hi) \
    asm("cvt.rn.satfinite.bf16x2.f32 %0, %1, %2;" : "=r"(result) : "f"(hi), "f"(lo))

#define PREFETCH_L2(addr) \
    asm volatile("prefetch.global.L2 [%0];" :: "l"(addr))

// W tile: 256B rows, 16B-unit swizzle u ^= (r&7)
__device__ __forceinline__ uint32_t swz_pair(int r, int p) {
    return (uint32_t)(r * 256 + ((((p >> 2) ^ (r & 7)) << 4) | ((p & 3) << 2)));
}
__device__ __forceinline__ uint32_t swz_unit(int r, int u) {
    return (uint32_t)(r * 256 + ((u ^ (r & 7)) << 4));
}

__device__ __forceinline__ void ldsm_x4(uint32_t& r0, uint32_t& r1, uint32_t& r2, uint32_t& r3,
                                        uint32_t addr) {
    asm volatile("ldmatrix.sync.aligned.m8n8.x4.shared.b16 {%0,%1,%2,%3}, [%4];"
                 : "=r"(r0), "=r"(r1), "=r"(r2), "=r"(r3) : "r"(addr));
}

__device__ __forceinline__ void mma16816(float* d, uint32_t a0, uint32_t a1, uint32_t a2,
                                         uint32_t a3, uint32_t b0, uint32_t b1) {
    asm volatile("mma.sync.aligned.m16n8k16.row.col.f32.bf16.bf16.f32 "
                 "{%0,%1,%2,%3}, {%4,%5,%6,%7}, {%8,%9}, {%0,%1,%2,%3};"
                 : "+f"(d[0]), "+f"(d[1]), "+f"(d[2]), "+f"(d[3])
                 : "r"(a0), "r"(a1), "r"(a2), "r"(a3), "r"(b0), "r"(b1));
}

// ---------------- main fused kernel ----------------

__global__ void __launch_bounds__(THREADS, 2)
fused_embed_segsum_kernel(const float* __restrict__ x,
                          const float* __restrict__ W,
                          const float* __restrict__ bias_v,
                          const int*   __restrict__ batch,    // int32
                          int nAtoms, int nTiles, int nSeg)
{
    extern __shared__ char smem[];
    const uint32_t smem_u = smem_to_u32(smem);
    const int tid  = threadIdx.x;
    const int wid  = tid >> 5;
    const int lane = tid & 31;

    float* h_sm     = reinterpret_cast<float*>(smem + SM_H);
    int*   batch_sm = reinterpret_cast<int*>(smem + SM_BATCH);
    const char* xbase = reinterpret_cast<const char*>(x);
    float* out_s = g_scratch;

    int segCap = nSeg;
    if (segCap * DOUT > SCRATCH_CAP) segCap = SCRATCH_CAP / DOUT;

    // ---- W -> bf16 swizzled smem (once) ----
    for (int idx = tid; idx < DOUT * NPAIR; idx += THREADS) {
        const int r = idx >> 6;        // out row 0..63
        const int p = idx & 63;        // k pair
        uint32_t u = 0;
        if (p < DATA_PAIRS) {
            float2 v = *reinterpret_cast<const float2*>(W + (size_t)r * DIN + 2 * p);
            CVT_BF16X2(u, v.x, v.y);
        }
        *reinterpret_cast<uint32_t*>(smem + SM_W + swz_pair(r, p)) = u;
    }

    // warp tiling: rows (wid&3)*16, cols (wid>>2)*32
    const int m0    = (wid & 3) * 16;
    const int nbase = (wid >> 2) * 32;

    // per-lane bias for epilogue cols nbase + nt*8 + 2*(lane&3) + {0,1}
    float2 bv[4];
    {
        const int c0 = nbase + 2 * (lane & 3);
        #pragma unroll
        for (int nt = 0; nt < 4; nt++)
            bv[nt] = *reinterpret_cast<const float2*>(bias_v + nt * 8 + c0);
    }
    __syncthreads();

    // ---- hoist W fragments into registers (constant across tiles) ----
    uint32_t bf[8][8];   // [ks][g*4 + j]
    #pragma unroll
    for (int ks = 0; ks < 8; ks++) {
        #pragma unroll
        for (int g = 0; g < 2; g++) {
            const int nr = nbase + g * 16 + ((lane >> 4) << 3) + (lane & 7);
            const int ub = 2 * ks + ((lane >> 3) & 1);
            ldsm_x4(bf[ks][g * 4 + 0], bf[ks][g * 4 + 1],
                    bf[ks][g * 4 + 2], bf[ks][g * 4 + 3],
                    smem_u + SM_W + swz_unit(nr, ub));
        }
    }

    // A-fragment row/col bases (row-major A, m16n8k16)
    const int rA0 = m0 + (lane >> 2);
    const int rA1 = rA0 + 8;
    const int kc  = 2 * (lane & 3);
    const bool kc_ok = (lane & 3) != 3;   // ks=7: k0=112+kc valid iff kc<6

    for (int t = blockIdx.x; t < nTiles; t += gridDim.x) {
        const int row0 = t * TILE;
        int valid = nAtoms - row0;
        if (valid > TILE) valid = TILE;

        // batch ids (LDG early; consumed after GEMM -> latency hidden)
        if (tid < TILE) {
            int v = 0;
            if (tid < valid) {
                v = batch[row0 + tid];
                if (v < 0) v = 0;
                if (v >= segCap) v = segCap - 1;
            }
            batch_sm[tid] = v;
        }

        // L2 prefetch of next tile (keeps DRAM pipe fed)
        {
            const int tn = t + gridDim.x;
            if (tn < nTiles) {
                int nv = nAtoms - tn * TILE;
                if (nv > TILE) nv = TILE;
                const int lines = (nv * XROW_BYTES + 127) >> 7;
                if (tid < lines)
                    PREFETCH_L2(xbase + (size_t)tn * XTILE_B + ((size_t)tid << 7));
            }
        }

        // ---- GEMM: A fragments straight from GLOBAL (LDG.64 + cvt), B from regs ----
        const float* pA0 = x + (size_t)(row0 + rA0) * DIN;
        const float* pA1 = pA0 + 8 * DIN;

        float acc[4][4];
        #pragma unroll
        for (int nt = 0; nt < 4; nt++)
            #pragma unroll
            for (int i = 0; i < 4; i++) acc[nt][i] = 0.0f;

        if (valid == TILE) {
            // fast path: no row bounds checks
            #pragma unroll
            for (int ks = 0; ks < 8; ks++) {
                const int k0 = 16 * ks + kc;
                uint32_t a0 = 0, a1 = 0, a2 = 0, a3 = 0;
                if (ks < 7) {
                    float2 v0 = *reinterpret_cast<const float2*>(pA0 + k0);
                    float2 v1 = *reinterpret_cast<const float2*>(pA1 + k0);
                    float2 v2 = *reinterpret_cast<const float2*>(pA0 + k0 + 8);
                    float2 v3 = *reinterpret_cast<const float2*>(pA1 + k0 + 8);
                    CVT_BF16X2(a0, v0.x, v0.y);
                    CVT_BF16X2(a1, v1.x, v1.y);
                    CVT_BF16X2(a2, v2.x, v2.y);
                    CVT_BF16X2(a3, v3.x, v3.y);
                } else if (kc_ok) {           // k0 = 112+kc < 118; k1 always OOB
                    float2 v0 = *reinterpret_cast<const float2*>(pA0 + k0);
                    float2 v1 = *reinterpret_cast<const float2*>(pA1 + k0);
                    CVT_BF16X2(a0, v0.x, v0.y);
                    CVT_BF16X2(a1, v1.x, v1.y);
                }
                mma16816(acc[0], a0, a1, a2, a3, bf[ks][0], bf[ks][1]);
                mma16816(acc[1], a0, a1, a2, a3, bf[ks][2], bf[ks][3]);
                mma16816(acc[2], a0, a1, a2, a3, bf[ks][4], bf[ks][5]);
                mma16816(acc[3], a0, a1, a2, a3, bf[ks][6], bf[ks][7]);
            }
        } else {
            // guarded path (last tile only)
            const bool rv0 = rA0 < valid;
            const bool rv1 = rA1 < valid;
            #pragma unroll
            for (int ks = 0; ks < 8; ks++) {
                const int k0 = 16 * ks + kc;
                const int k1 = k0 + 8;
                uint32_t a0 = 0, a1 = 0, a2 = 0, a3 = 0;
                if (rv0 && k0 < DIN) { float2 v = *reinterpret_cast<const float2*>(pA0 + k0); CVT_BF16X2(a0, v.x, v.y); }
                if (rv1 && k0 < DIN) { float2 v = *reinterpret_cast<const float2*>(pA1 + k0); CVT_BF16X2(a1, v.x, v.y); }
                if (rv0 && k1 < DIN) { float2 v = *reinterpret_cast<const float2*>(pA0 + k1); CVT_BF16X2(a2, v.x, v.y); }
                if (rv1 && k1 < DIN) { float2 v = *reinterpret_cast<const float2*>(pA1 + k1); CVT_BF16X2(a3, v.x, v.y); }
                mma16816(acc[0], a0, a1, a2, a3, bf[ks][0], bf[ks][1]);
                mma16816(acc[1], a0, a1, a2, a3, bf[ks][2], bf[ks][3]);
                mma16816(acc[2], a0, a1, a2, a3, bf[ks][4], bf[ks][5]);
                mma16816(acc[3], a0, a1, a2, a3, bf[ks][6], bf[ks][7]);
            }
        }

        // ---- bias + relu -> h_sm ----
        {
            const int rbase = m0 + (lane >> 2);
            const int c0 = nbase + 2 * (lane & 3);
            #pragma unroll
            for (int nt = 0; nt < 4; nt++) {
                float2 h0, h1;
                h0.x = fmaxf(acc[nt][0] + bv[nt].x, 0.0f);
                h0.y = fmaxf(acc[nt][1] + bv[nt].y, 0.0f);
                h1.x = fmaxf(acc[nt][2] + bv[nt].x, 0.0f);
                h1.y = fmaxf(acc[nt][3] + bv[nt].y, 0.0f);
                *reinterpret_cast<float2*>(h_sm + rbase * HSTRIDE + nt * 8 + c0) = h0;
                *reinterpret_cast<float2*>(h_sm + (rbase + 8) * HSTRIDE + nt * 8 + c0) = h1;
            }
        }
        __syncthreads();

        // ---- sorted-segment run-length reduction into g_scratch ----
        // 8 warps; warp w handles atoms [w*8, w*8+8); each lane owns 2 cols.
        {
            const int o2 = 2 * lane;               // columns o2, o2+1
            const int cbase = wid * 8;
            if (cbase < valid) {
                int cend = cbase + 8;
                if (cend > valid) cend = valid;
                int cur = batch_sm[cbase];
                float2 acc2 = make_float2(0.0f, 0.0f);
                for (int c = cbase; c < cend; c++) {
                    const int seg = batch_sm[c];      // LDS broadcast, warp-uniform
                    if (seg != cur) {                 // warp-uniform branch
                        atomicAdd(out_s + (size_t)cur * DOUT + o2,     acc2.x);
                        atomicAdd(out_s + (size_t)cur * DOUT + o2 + 1, acc2.y);
                        acc2.x = 0.0f; acc2.y = 0.0f;
                        cur = seg;
                    }
                    float2 hv = *reinterpret_cast<const float2*>(h_sm + c * HSTRIDE + o2);
                    acc2.x += hv.x;
                    acc2.y += hv.y;
                }
                atomicAdd(out_s + (size_t)cur * DOUT + o2,     acc2.x);
                atomicAdd(out_s + (size_t)cur * DOUT + o2 + 1, acc2.y);
            }
        }
        __syncthreads();   // h_sm / batch_sm reuse next iteration
    }
}

// ---------------- relu + row-max normalize (consumes & re-zeroes scratch) ----------------
// 128 threads/block; each 16-lane half-warp owns one graph (64 f32 = 16 x float4).

__global__ void normalize_kernel(float* __restrict__ out, int nSeg)
{
    const int half = threadIdx.x >> 4;           // 0..7 half-warps per block
    const int hl   = threadIdx.x & 15;
    const int g    = blockIdx.x * 8 + half;
    if (g >= nSeg) return;
    const size_t base = (size_t)g * DOUT + hl * 4;
    float4 v = *reinterpret_cast<float4*>(g_scratch + base);
    *reinterpret_cast<float4*>(g_scratch + base) = make_float4(0.f, 0.f, 0.f, 0.f);
    v.x = fmaxf(v.x, 0.0f); v.y = fmaxf(v.y, 0.0f);
    v.z = fmaxf(v.z, 0.0f); v.w = fmaxf(v.w, 0.0f);
    float m = fmaxf(fmaxf(v.x, v.y), fmaxf(v.z, v.w));
    #pragma unroll
    for (int off = 8; off > 0; off >>= 1)
        m = fmaxf(m, __shfl_xor_sync(0xffffffff, m, off));
    float4 r;
    r.x = v.x / m; r.y = v.y / m; r.z = v.z / m; r.w = v.w / m;
    *reinterpret_cast<float4*>(out + base) = r;
}

// ---------------- launch ----------------

extern "C" void kernel_launch(void* const* d_in, const int* in_sizes, int n_in,
                              void* d_out, int out_size)
{
    const float* x     = (const float*)d_in[0];
    const float* W     = (const float*)d_in[1];
    const float* b     = (const float*)d_in[2];
    const int*   batch = (const int*)d_in[3];
    float* out = (float*)d_out;

    const int nAtoms = in_sizes[0] / DIN;
    const int nSeg   = out_size / DOUT;
    const int nTiles = (nAtoms + TILE - 1) / TILE;

    cudaFuncSetAttribute(fused_embed_segsum_kernel,
                         cudaFuncAttributeMaxDynamicSharedMemorySize, SMEM_TOTAL);

    int grid = 296;                    // 2 CTAs/SM, persistent
    if (grid > nTiles) grid = nTiles;

    fused_embed_segsum_kernel<<<grid, THREADS, SMEM_TOTAL>>>(
        x, W, b, batch, nAtoms, nTiles, nSeg);
    normalize_kernel<<<(nSeg + 7) / 8, 128>>>(out, nSeg);
}

// round 11
// speedup vs baseline: 1.5582x; 1.5582x over previous
#include <cuda_runtime.h>
#include <cuda_bf16.h>
#include <cstdint>

#define DIN        118
#define DOUT       64
#define TILE       32
#define THREADS    128
#define HSTRIDE    72        // floats per h row (padding vs bank conflicts)
#define XROW_BYTES 472       // 118 * 4
#define XTILE_B    (TILE * XROW_BYTES)   // 15104, 16B-multiple
#define NSTAGE     3

// dynamic smem layout (bytes)
#define SM_H      0                       // f32  [32][72]            = 9216
#define SM_BATCH  9216                    // int  [32] clamped        = 128
#define SM_MBAR   9344                    // 3 x 8B mbarriers (+pad)  = 32
#define SM_BSTG   9376                    // raw batch staging 3x128  = 384
#define SM_STG    9760                    // f32 staging 3 x 15104 (16B aligned)
#define SMEM_TOTAL (SM_STG + NSTAGE * XTILE_B)   // 55072

// segment-sum scratch (consumed & re-zeroed by normalize -> graph-replay safe)
#define SCRATCH_CAP (1 << 20)             // 4 MB: supports nSeg <= 16384
__device__ float g_scratch[SCRATCH_CAP];

// ---------------- helpers ----------------

__device__ __forceinline__ uint32_t smem_to_u32(const void* p) {
    uint32_t a;
    asm("{ .reg .u64 t; cvta.to.shared.u64 t, %1; cvt.u32.u64 %0, t; }"
        : "=r"(a) : "l"(p));
    return a;
}

#define CVT_BF16X2(result, lo, hi) \
    asm("cvt.rn.satfinite.bf16x2.f32 %0, %1, %2;" : "=r"(result) : "f"(hi), "f"(lo))

#define MBARRIER_INIT(mbar, count) \
    asm volatile("mbarrier.init.shared.b64 [%0], %1;" \
                 :: "r"((uint32_t)(mbar)), "r"((uint32_t)(count)) : "memory")

#define MBARRIER_EXPECT_TX(mbar, tx_bytes) \
    asm volatile("mbarrier.arrive.expect_tx.shared.b64 _, [%0], %1;" \
                 :: "r"((uint32_t)(mbar)), "r"((uint32_t)(tx_bytes)) : "memory")

#define MBARRIER_WAIT_PARITY(mbar, parity) do {                                   \
    uint32_t _m = (uint32_t)(mbar);                                               \
    uint32_t _p = (uint32_t)(parity);                                             \
    uint32_t _done;                                                               \
    asm volatile("{\n\t.reg .pred p;\n\t"                                         \
        "mbarrier.try_wait.parity.acquire.cta.shared::cta.b64 p, [%1], %2;\n\t"   \
        "selp.b32 %0, 1, 0, p;\n\t}"                                              \
        : "=r"(_done) : "r"(_m), "r"(_p) : "memory");                             \
    if (!_done) {                                                                 \
        asm volatile("{\n\t.reg .pred P1;\n\t"                                    \
            "WAIT_LOOP_%=:\n\t"                                                   \
            "mbarrier.try_wait.parity.acquire.cta.shared::cta.b64 P1, [%0], %1, 0x989680;\n\t" \
            "@P1 bra.uni WAIT_DONE_%=;\n\t"                                       \
            "bra.uni WAIT_LOOP_%=;\n\t"                                           \
            "WAIT_DONE_%=:\n\t}"                                                  \
            :: "r"(_m), "r"(_p) : "memory");                                      \
    }                                                                             \
} while (0)

// single bulk async copy: global -> shared, completion via mbarrier tx-bytes
#define CP_BULK(dst_smem, src_gmem, nbytes, mbar) \
    asm volatile("cp.async.bulk.shared::cluster.global.mbarrier::complete_tx::bytes " \
                 "[%0], [%1], %2, [%3];" \
                 :: "r"((uint32_t)(dst_smem)), "l"(src_gmem), \
                    "r"((uint32_t)(nbytes)), "r"((uint32_t)(mbar)) : "memory")

__device__ __forceinline__ void mma16816(float* d, uint32_t a0, uint32_t a1, uint32_t a2,
                                         uint32_t a3, uint32_t b0, uint32_t b1) {
    asm volatile("mma.sync.aligned.m16n8k16.row.col.f32.bf16.bf16.f32 "
                 "{%0,%1,%2,%3}, {%4,%5,%6,%7}, {%8,%9}, {%0,%1,%2,%3};"
                 : "+f"(d[0]), "+f"(d[1]), "+f"(d[2]), "+f"(d[3])
                 : "r"(a0), "r"(a1), "r"(a2), "r"(a3), "r"(b0), "r"(b1));
}

// issue bulk copies (x tile + batch ids) for one tile into staging buffer `buf`
__device__ __forceinline__ void issue_tile(const char* xbase, const char* bbase,
                                           uint32_t smem_u, int buf,
                                           int tile, int nAtoms)
{
    int valid = nAtoms - tile * TILE;
    if (valid > TILE) valid = TILE;
    const uint32_t xb16 = (uint32_t)(valid * XROW_BYTES) & ~15u;
    const uint32_t bb16 = (uint32_t)(valid * 4) & ~15u;
    const uint32_t mb = smem_u + SM_MBAR + 8u * (uint32_t)buf;
    MBARRIER_EXPECT_TX(mb, xb16 + bb16);
    CP_BULK(smem_u + SM_STG + buf * XTILE_B,
            xbase + (size_t)tile * XTILE_B, xb16, mb);
    if (bb16)
        CP_BULK(smem_u + SM_BSTG + buf * 128,
                bbase + (size_t)tile * TILE * 4, bb16, mb);
}

// ---------------- main fused kernel ----------------

__global__ void __launch_bounds__(THREADS, 4)
fused_embed_segsum_kernel(const float* __restrict__ x,
                          const float* __restrict__ W,
                          const float* __restrict__ bias_v,
                          const int*   __restrict__ batch,    // int32
                          int nAtoms, int nTiles, int nSeg)
{
    extern __shared__ char smem[];
    const uint32_t smem_u = smem_to_u32(smem);
    const int tid  = threadIdx.x;
    const int wid  = tid >> 5;    // 0..3
    const int lane = tid & 31;

    float* h_sm     = reinterpret_cast<float*>(smem + SM_H);
    int*   batch_sm = reinterpret_cast<int*>(smem + SM_BATCH);
    const char* xbase = reinterpret_cast<const char*>(x);
    const char* bbase = reinterpret_cast<const char*>(batch);
    float* out_s = g_scratch;

    int segCap = nSeg;
    if (segCap * DOUT > SCRATCH_CAP) segCap = SCRATCH_CAP / DOUT;

    // ---- init mbarriers; issue copies of first two tiles (buf 0, 1) ----
    if (tid == 0) {
        MBARRIER_INIT(smem_u + SM_MBAR, 1);
        MBARRIER_INIT(smem_u + SM_MBAR + 8, 1);
        MBARRIER_INIT(smem_u + SM_MBAR + 16, 1);
    }
    __syncthreads();

    const int t0 = blockIdx.x;
    if (tid == 0) {
        if (t0 < nTiles)              issue_tile(xbase, bbase, smem_u, 0, t0, nAtoms);
        if (t0 + gridDim.x < nTiles)  issue_tile(xbase, bbase, smem_u, 1, t0 + gridDim.x, nAtoms);
    }

    // warp tiling: rows (wid&1)*16, cols (wid>>1)*32
    const int m0    = (wid & 1) * 16;
    const int nbase = (wid >> 1) * 32;

    // ---- W fragments straight from global (canonical m16n8k16 B layout) ----
    // b0 = W[n][k0..k0+1], b1 = W[n][k0+8..k0+9]; n = ntile*8 + lane/4, k0 = 16ks + 2*(lane%4)
    uint32_t bf[8][8];   // [ks][j*2 + {lo,hi}]
    {
        const int kcw = 2 * (lane & 3);
        #pragma unroll
        for (int ks = 0; ks < 8; ks++) {
            const int k0 = 16 * ks + kcw;
            const int k1 = k0 + 8;
            #pragma unroll
            for (int j = 0; j < 4; j++) {
                const int n = nbase + j * 8 + (lane >> 2);
                const float* wr = W + (size_t)n * DIN;
                uint32_t lo = 0, hi = 0;
                if (k0 < DIN) { float2 v = *reinterpret_cast<const float2*>(wr + k0); CVT_BF16X2(lo, v.x, v.y); }
                if (k1 < DIN) { float2 v = *reinterpret_cast<const float2*>(wr + k1); CVT_BF16X2(hi, v.x, v.y); }
                bf[ks][j * 2]     = lo;
                bf[ks][j * 2 + 1] = hi;
            }
        }
    }

    // per-lane bias for epilogue cols nbase + nt*8 + 2*(lane&3) + {0,1}
    float2 bv[4];
    {
        const int c0 = nbase + 2 * (lane & 3);
        #pragma unroll
        for (int nt = 0; nt < 4; nt++)
            bv[nt] = *reinterpret_cast<const float2*>(bias_v + nt * 8 + c0);
    }

    // A-fragment row/col bases (row-major A, m16n8k16)
    const int rA0 = m0 + (lane >> 2);
    const int rA1 = rA0 + 8;
    const int kc  = 2 * (lane & 3);

    int buf = 0, nxt2 = 2, wrap = 0;
    for (int t = t0; t < nTiles; t += gridDim.x) {
        const int row0 = t * TILE;
        int valid = nAtoms - row0;
        if (valid > TILE) valid = TILE;
        const float* stg_f = reinterpret_cast<const float*>(smem + SM_STG + buf * XTILE_B);
        const int* bstg = reinterpret_cast<const int*>(smem + SM_BSTG + buf * 128);

        // 1) issue copy 2 tiles ahead into nxt2 (that buffer drained last iteration)
        const int tn = t + 2 * gridDim.x;
        if (tid == 0 && tn < nTiles)
            issue_tile(xbase, bbase, smem_u, nxt2, tn, nAtoms);

        // 2) wait for CURRENT tile's copies; clamp batch ids; patch tails
        MBARRIER_WAIT_PARITY(smem_u + SM_MBAR + 8u * (uint32_t)buf, wrap);
        if (tid < TILE) {
            int v = 0;
            if (tid < valid) {
                // staged unless in the (rare, last-tile) 16B-rounding tail
                v = (((tid + 1) * 4) <= ((valid * 4) & ~15)) ? bstg[tid]
                                                             : batch[row0 + tid];
                if (v < 0) v = 0;
                if (v >= segCap) v = segCap - 1;
            }
            batch_sm[tid] = v;
        }
        {
            const int bytes = valid * XROW_BYTES;
            if (tid == 0 && (bytes & 15)) {   // odd 'valid' -> 8B x tail
                const int off = bytes & ~15;
                float2 v = *reinterpret_cast<const float2*>(
                    xbase + (size_t)row0 * XROW_BYTES + off);
                *reinterpret_cast<float2*>(const_cast<float*>(stg_f) + off / 4) = v;
            }
        }
        __syncthreads();

        // 3) GEMM: A fragments from f32 staging (LDS.64 + cvt), B from regs
        const bool rv0 = rA0 < valid;
        const bool rv1 = rA1 < valid;
        const float* pA0 = stg_f + rA0 * DIN;
        const float* pA1 = stg_f + rA1 * DIN;

        float acc[4][4];
        #pragma unroll
        for (int nt = 0; nt < 4; nt++)
            #pragma unroll
            for (int i = 0; i < 4; i++) acc[nt][i] = 0.0f;

        #pragma unroll
        for (int ks = 0; ks < 8; ks++) {
            const int k0 = 16 * ks + kc;
            const int k1 = k0 + 8;
            uint32_t a0 = 0, a1 = 0, a2 = 0, a3 = 0;
            if (rv0 && k0 < DIN) { float2 v = *reinterpret_cast<const float2*>(pA0 + k0); CVT_BF16X2(a0, v.x, v.y); }
            if (rv1 && k0 < DIN) { float2 v = *reinterpret_cast<const float2*>(pA1 + k0); CVT_BF16X2(a1, v.x, v.y); }
            if (rv0 && k1 < DIN) { float2 v = *reinterpret_cast<const float2*>(pA0 + k1); CVT_BF16X2(a2, v.x, v.y); }
            if (rv1 && k1 < DIN) { float2 v = *reinterpret_cast<const float2*>(pA1 + k1); CVT_BF16X2(a3, v.x, v.y); }
            mma16816(acc[0], a0, a1, a2, a3, bf[ks][0], bf[ks][1]);
            mma16816(acc[1], a0, a1, a2, a3, bf[ks][2], bf[ks][3]);
            mma16816(acc[2], a0, a1, a2, a3, bf[ks][4], bf[ks][5]);
            mma16816(acc[3], a0, a1, a2, a3, bf[ks][6], bf[ks][7]);
        }

        // 4) bias + relu -> h_sm
        {
            const int rbase = m0 + (lane >> 2);
            const int c0 = nbase + 2 * (lane & 3);
            #pragma unroll
            for (int nt = 0; nt < 4; nt++) {
                float2 h0, h1;
                h0.x = fmaxf(acc[nt][0] + bv[nt].x, 0.0f);
                h0.y = fmaxf(acc[nt][1] + bv[nt].y, 0.0f);
                h1.x = fmaxf(acc[nt][2] + bv[nt].x, 0.0f);
                h1.y = fmaxf(acc[nt][3] + bv[nt].y, 0.0f);
                *reinterpret_cast<float2*>(h_sm + rbase * HSTRIDE + nt * 8 + c0) = h0;
                *reinterpret_cast<float2*>(h_sm + (rbase + 8) * HSTRIDE + nt * 8 + c0) = h1;
            }
        }
        __syncthreads();

        // 5) sorted-segment run-length reduction into g_scratch:
        //    4 warps; warp w handles atoms [w*8, w*8+8); each lane owns 2 cols.
        {
            const int o2 = 2 * lane;
            const int cbase = wid * 8;
            if (cbase < valid) {
                int cend = cbase + 8;
                if (cend > valid) cend = valid;
                int cur = batch_sm[cbase];
                float2 acc2 = make_float2(0.0f, 0.0f);
                for (int c = cbase; c < cend; c++) {
                    const int seg = batch_sm[c];      // LDS broadcast, warp-uniform
                    if (seg != cur) {                 // warp-uniform branch
                        atomicAdd(out_s + (size_t)cur * DOUT + o2,     acc2.x);
                        atomicAdd(out_s + (size_t)cur * DOUT + o2 + 1, acc2.y);
                        acc2.x = 0.0f; acc2.y = 0.0f;
                        cur = seg;
                    }
                    float2 hv = *reinterpret_cast<const float2*>(h_sm + c * HSTRIDE + o2);
                    acc2.x += hv.x;
                    acc2.y += hv.y;
                }
                atomicAdd(out_s + (size_t)cur * DOUT + o2,     acc2.x);
                atomicAdd(out_s + (size_t)cur * DOUT + o2 + 1, acc2.y);
            }
        }
        __syncthreads();   // h_sm / batch_sm reuse; staging(buf) rearm next iter

        // advance ring (parity of a buffer flips each wrap)
        if (++buf == NSTAGE) { buf = 0; wrap ^= 1; }
        if (++nxt2 == NSTAGE) nxt2 = 0;
    }
}

// ---------------- relu + row-max normalize (consumes & re-zeroes scratch) ----------------
// 128 threads/block; each 16-lane half-warp owns one graph (64 f32 = 16 x float4).

__global__ void normalize_kernel(float* __restrict__ out, int nSeg)
{
    const int half = threadIdx.x >> 4;           // 0..7 half-warps per block
    const int hl   = threadIdx.x & 15;
    const int g    = blockIdx.x * 8 + half;
    if (g >= nSeg) return;
    const size_t base = (size_t)g * DOUT + hl * 4;
    float4 v = *reinterpret_cast<float4*>(g_scratch + base);
    *reinterpret_cast<float4*>(g_scratch + base) = make_float4(0.f, 0.f, 0.f, 0.f);
    v.x = fmaxf(v.x, 0.0f); v.y = fmaxf(v.y, 0.0f);
    v.z = fmaxf(v.z, 0.0f); v.w = fmaxf(v.w, 0.0f);
    float m = fmaxf(fmaxf(v.x, v.y), fmaxf(v.z, v.w));
    #pragma unroll
    for (int off = 8; off > 0; off >>= 1)
        m = fmaxf(m, __shfl_xor_sync(0xffffffff, m, off));
    float4 r;
    r.x = v.x / m; r.y = v.y / m; r.z = v.z / m; r.w = v.w / m;
    *reinterpret_cast<float4*>(out + base) = r;
}

// ---------------- launch ----------------

extern "C" void kernel_launch(void* const* d_in, const int* in_sizes, int n_in,
                              void* d_out, int out_size)
{
    const float* x     = (const float*)d_in[0];
    const float* W     = (const float*)d_in[1];
    const float* b     = (const float*)d_in[2];
    const int*   batch = (const int*)d_in[3];
    float* out = (float*)d_out;

    const int nAtoms = in_sizes[0] / DIN;
    const int nSeg   = out_size / DOUT;
    const int nTiles = (nAtoms + TILE - 1) / TILE;

    cudaFuncSetAttribute(fused_embed_segsum_kernel,
                         cudaFuncAttributeMaxDynamicSharedMemorySize, SMEM_TOTAL);

    int grid = 592;                    // 4 CTAs/SM, persistent
    if (grid > nTiles) grid = nTiles;

    fused_embed_segsum_kernel<<<grid, THREADS, SMEM_TOTAL>>>(
        x, W, b, batch, nAtoms, nTiles, nSeg);
    normalize_kernel<<<(nSeg + 7) / 8, 128>>>(out, nSeg);
}